// round 4
// baseline (speedup 1.0000x reference)
#include <cuda_runtime.h>

// Problem constants (B, N, M, d) = (32, 4096, 4096, 3)
#define BB 32
#define NN 4096
#define MM 4096
#define NCHUNK 4            // n-chunks per batch
#define MHALF  4            // m split per batch
#define NPB (NN / NCHUNK)   // 1024 preds per CTA
#define TPB 128             // threads per CTA
#define PPT (NPB / TPB)     // 8 preds per thread
#define NPAIR (PPT / 2)     // 4 packed pred pairs per thread
#define MSEG (MM / MHALF)   // 1024 targets per CTA tile

#define RBLK 256            // reduce-1 blocks

typedef unsigned long long u64;

// Scratch (no allocations allowed in kernel_launch)
__device__ ulonglong2 g_tA[BB * MM];          // { {x,x}, {y,y} } per target
__device__ ulonglong2 g_tB[BB * MM];          // { {z,z}, {w,w} },  w = 0.5*|t|^2
__device__ float      g_pmin[BB * NN * MHALF];// partial mins per (b,n,mh)
__device__ float      g_bsum[RBLK];           // block partial sums

// ---- packed f32x2 helpers ------------------------------------------------
__device__ __forceinline__ u64 pk2(float lo, float hi) {
    u64 r;
    asm("mov.b64 %0, {%1, %2};" : "=l"(r) : "f"(lo), "f"(hi));
    return r;
}
__device__ __forceinline__ void upk2(float& lo, float& hi, u64 v) {
    asm("mov.b64 {%0, %1}, %2;" : "=f"(lo), "=f"(hi) : "l"(v));
}
__device__ __forceinline__ u64 fma2(u64 a, u64 b, u64 c) {
    u64 d;
    asm("fma.rn.f32x2 %0, %1, %2, %3;" : "=l"(d) : "l"(a), "l"(b), "l"(c));
    return d;
}

// ---------------------------------------------------------------------------
// Pack targets: duplicate each component into a f32x2 lane pair so the main
// loop needs zero broadcast/packing instructions.
// ---------------------------------------------------------------------------
__global__ void pack_targets_kernel(const float* __restrict__ tgt) {
    int i = blockIdx.x * blockDim.x + threadIdx.x;
    if (i < BB * MM) {
        float x = tgt[3 * i + 0];
        float y = tgt[3 * i + 1];
        float z = tgt[3 * i + 2];
        float w = 0.5f * (x * x + y * y + z * z);
        ulonglong2 A, B;
        A.x = pk2(x, x); A.y = pk2(y, y);
        B.x = pk2(z, z); B.y = pk2(w, w);
        g_tA[i] = A;
        g_tB[i] = B;
    }
}

// ---------------------------------------------------------------------------
// Main kernel: r = t2/2 - p.t per (pred, target);  d2 = p2 + 2*min r later.
// Packed: each FFMA2 serves two preds. Per target per thread:
//   2 x LDS.128  +  12 FFMA2 (fma pipe)  +  8 FMNMX (alu pipe)
// ---------------------------------------------------------------------------
__global__ __launch_bounds__(TPB) void chamfer_min_kernel(const float* __restrict__ pred) {
    __shared__ ulonglong2 sA[MSEG];   // 16 KB
    __shared__ ulonglong2 sB[MSEG];   // 16 KB

    int bx     = blockIdx.x;
    int b      = bx >> 4;             // 16 = NCHUNK * MHALF
    int nchunk = (bx >> 2) & 3;
    int mh     = bx & 3;

    // Stage this CTA's duplicated target tile
    const ulonglong2* gA = g_tA + b * MM + mh * MSEG;
    const ulonglong2* gB = g_tB + b * MM + mh * MSEG;
    #pragma unroll
    for (int i = threadIdx.x; i < MSEG; i += TPB) {
        sA[i] = gA[i];
        sB[i] = gB[i];
    }
    __syncthreads();

    // Pack this thread's 8 preds into 4 negated f32x2 pairs (loop invariant)
    u64 nx[NPAIR], ny[NPAIR], nz[NPAIR];
    float m[PPT];
    int n0 = nchunk * NPB + threadIdx.x;
    #pragma unroll
    for (int j = 0; j < NPAIR; j++) {
        const float* pa = pred + (size_t)(b * NN + n0 + (2 * j)     * TPB) * 3;
        const float* pb = pred + (size_t)(b * NN + n0 + (2 * j + 1) * TPB) * 3;
        nx[j] = pk2(-pa[0], -pb[0]);
        ny[j] = pk2(-pa[1], -pb[1]);
        nz[j] = pk2(-pa[2], -pb[2]);
        m[2 * j]     = 3.4028235e38f;
        m[2 * j + 1] = 3.4028235e38f;
    }

    // Main loop — fma-pipe bound via FFMA2
    #pragma unroll 4
    for (int i = 0; i < MSEG; i++) {
        ulonglong2 A = sA[i];   // {xx, yy}
        ulonglong2 B = sB[i];   // {zz, ww}
        #pragma unroll
        for (int j = 0; j < NPAIR; j++) {
            u64 r = fma2(nz[j], B.x, B.y);
            r     = fma2(ny[j], A.y, r);
            r     = fma2(nx[j], A.x, r);
            float rlo, rhi;
            upk2(rlo, rhi, r);
            m[2 * j]     = fminf(m[2 * j],     rlo);
            m[2 * j + 1] = fminf(m[2 * j + 1], rhi);
        }
    }

    #pragma unroll
    for (int k = 0; k < PPT; k++) {
        int n = n0 + k * TPB;
        g_pmin[(size_t)(b * NN + n) * MHALF + mh] = m[k];
    }
}

// ---------------------------------------------------------------------------
// Reduction stage 1: combine 4 m-partials, d = sqrt(max(p2 + 2m, 0)),
// deterministic tree-sum per block.
// ---------------------------------------------------------------------------
__global__ __launch_bounds__(256) void reduce1_kernel(const float* __restrict__ pred) {
    __shared__ float ssum[256];
    int tid = threadIdx.x;
    const int per_block = (BB * NN) / RBLK;  // 512
    float acc = 0.0f;
    #pragma unroll
    for (int k = 0; k < per_block / 256; k++) {
        int i = blockIdx.x * per_block + k * 256 + tid;
        const float* p = pred + (size_t)i * 3;
        float x = p[0], y = p[1], z = p[2];
        float p2 = x * x + y * y + z * z;
        float4 mv = *((const float4*)&g_pmin[(size_t)i * MHALF]);
        float mm = fminf(fminf(mv.x, mv.y), fminf(mv.z, mv.w));
        float d2 = fmaxf(__fmaf_rn(2.0f, mm, p2), 0.0f);
        acc += sqrtf(d2);
    }
    ssum[tid] = acc;
    __syncthreads();
    #pragma unroll
    for (int s = 128; s > 0; s >>= 1) {
        if (tid < s) ssum[tid] += ssum[tid + s];
        __syncthreads();
    }
    if (tid == 0) g_bsum[blockIdx.x] = ssum[0];
}

// ---------------------------------------------------------------------------
// Reduction stage 2: sum block partials, divide by B*N (deterministic)
// ---------------------------------------------------------------------------
__global__ __launch_bounds__(RBLK) void reduce2_kernel(float* __restrict__ out) {
    __shared__ float ssum[RBLK];
    int tid = threadIdx.x;
    ssum[tid] = g_bsum[tid];
    __syncthreads();
    #pragma unroll
    for (int s = RBLK / 2; s > 0; s >>= 1) {
        if (tid < s) ssum[tid] += ssum[tid + s];
        __syncthreads();
    }
    if (tid == 0) out[0] = ssum[0] * (1.0f / (float)(BB * NN));
}

// ---------------------------------------------------------------------------
extern "C" void kernel_launch(void* const* d_in, const int* in_sizes, int n_in,
                              void* d_out, int out_size) {
    const float* pred   = (const float*)d_in[0];   // [B, N, 3] f32
    const float* target = (const float*)d_in[1];   // [B, M, 3] f32
    float* out = (float*)d_out;

    pack_targets_kernel<<<(BB * MM + 255) / 256, 256>>>(target);
    chamfer_min_kernel<<<BB * NCHUNK * MHALF, TPB>>>(pred);
    reduce1_kernel<<<RBLK, 256>>>(pred);
    reduce2_kernel<<<1, RBLK>>>(out);
}